// round 8
// baseline (speedup 1.0000x reference)
#include <cuda_runtime.h>

// Problem constants
#define BI 4
#define SS 1024
#define DM 1024
#define NH 16
#define DH 64
#define MROWS (BI * SS)            // 4096
#define OUT_ELEMS (MROWS * DM)     // 4194304
#define ATTN_ELEMS ((size_t)BI * NH * SS * SS)

// Scratch (device globals; allocation inside kernel_launch is forbidden)
__device__ float g_xq[MROWS * DM];   // tf32-rounded Qin
__device__ float g_xk[MROWS * DM];   // tf32-rounded Kin
__device__ float g_xv[MROWS * DM];   // tf32-rounded Vin
__device__ float g_wq[DM * DM];      // tf32-rounded weights
__device__ float g_wk[DM * DM];
__device__ float g_wv[DM * DM];
__device__ float g_wo[DM * DM];
__device__ float g_q[MROWS * DM];    // projections (tf32-rounded values)
__device__ float g_k[MROWS * DM];
__device__ float g_v[MROWS * DM];
__device__ float g_ctx[MROWS * DM];  // tf32-rounded context
__device__ float g_y[MROWS * DM];    // pre-LN (fp32)
__device__ float g_attn[ATTN_ELEMS]; // only used if attn not in d_out
__device__ int   g_mask_is_int32;

// ---------------------------------------------------------------------------
// tf32 + cp.async helpers
// ---------------------------------------------------------------------------
__device__ __forceinline__ float f2tf(float x) {
    unsigned u;
    asm("cvt.rna.tf32.f32 %0, %1;" : "=r"(u) : "f"(x));
    return __uint_as_float(u);
}
__device__ __forceinline__ float4 tf32x4(float4 v) {
    return make_float4(f2tf(v.x), f2tf(v.y), f2tf(v.z), f2tf(v.w));
}
__device__ __forceinline__ void cpa16(const void* smem_dst, const void* gmem_src) {
    unsigned d = (unsigned)__cvta_generic_to_shared(smem_dst);
    asm volatile("cp.async.ca.shared.global [%0], [%1], 16;" :: "r"(d), "l"(gmem_src));
}
#define CPC    asm volatile("cp.async.commit_group;")
#define CPW(n) asm volatile("cp.async.wait_group %0;" :: "n"(n))

#define MMA_TF32(d, a, b0, b1) \
    asm volatile("mma.sync.aligned.m16n8k8.row.col.f32.tf32.tf32.f32 " \
                 "{%0,%1,%2,%3}, {%4,%5,%6,%7}, {%8,%9}, {%0,%1,%2,%3};" \
                 : "+f"(d[0]), "+f"(d[1]), "+f"(d[2]), "+f"(d[3]) \
                 : "r"(a[0]), "r"(a[1]), "r"(a[2]), "r"(a[3]), "r"(b0), "r"(b1))

// ---------------------------------------------------------------------------
// Mask dtype detection: int32 (values 0/1) vs uint8 bytes.
// ---------------------------------------------------------------------------
__global__ void detect_mask_kernel(const unsigned* m) {
    int ok = 1;
    for (int i = threadIdx.x; i < 1024; i += 32)
        if (m[i] > 1u) ok = 0;
    unsigned b = __ballot_sync(0xffffffffu, ok);
    if (threadIdx.x == 0) g_mask_is_int32 = (b == 0xffffffffu) ? 1 : 0;
}

// ---------------------------------------------------------------------------
// Pre-round operands to tf32 once.
// ---------------------------------------------------------------------------
__global__ void round_inputs_kernel(const float* __restrict__ Q,
                                    const float* __restrict__ K,
                                    const float* __restrict__ V) {
    const float* s = blockIdx.z == 0 ? Q : blockIdx.z == 1 ? K : V;
    float* d = blockIdx.z == 0 ? g_xq : blockIdx.z == 1 ? g_xk : g_xv;
    size_t i = (size_t)blockIdx.x * blockDim.x + threadIdx.x;
    ((float4*)d)[i] = tf32x4(((const float4*)s)[i]);
}
__global__ void round_weights_kernel(const float* __restrict__ Wq,
                                     const float* __restrict__ Wk,
                                     const float* __restrict__ Wv,
                                     const float* __restrict__ Wo) {
    const float* s = blockIdx.z == 0 ? Wq : blockIdx.z == 1 ? Wk :
                     blockIdx.z == 2 ? Wv : Wo;
    float* d = blockIdx.z == 0 ? g_wq : blockIdx.z == 1 ? g_wk :
               blockIdx.z == 2 ? g_wv : g_wo;
    size_t i = (size_t)blockIdx.x * blockDim.x + threadIdx.x;
    ((float4*)d)[i] = tf32x4(((const float4*)s)[i]);
}

// ---------------------------------------------------------------------------
// 3-stage cp.async pipelined tf32 GEMM body (operands pre-rounded to tf32).
// 256 threads = 8 warps arranged MW x (8/MW); warp tile = (MF*16) x (NF*8).
// BM = MW*MF*16, BN = (8/MW)*NF*8.
// A smem: [m][20]  — frag banks (20r + cq) % 32 all-distinct.
// B smem: [k][BNS], BNS % 32 == 8 — frag banks (8cq + r) % 32 all-distinct.
// One __syncthreads per 16-wide K chunk; cp.async ring depth 3.
// ---------------------------------------------------------------------------
template<int MW, int MF, int NF, int BNS>
__device__ __forceinline__ void gemm_pipe(
    const float* __restrict__ A, int lda,
    const float* __restrict__ B, int ldb,
    int K, float* __restrict__ sm,
    float (&acc)[MF][NF][4])
{
    constexpr int BM = MW * MF * 16;
    constexpr int BN = (8 / MW) * NF * 8;
    constexpr int STG = BM * 20 + 16 * BNS;  // floats per stage
    constexpr int LA = BM / 64;              // A float4 per thread per chunk
    constexpr int LB = BN / 64;              // B float4 per thread per chunk
    const int tid = threadIdx.x;
    const int lane = tid & 31, wid = tid >> 5;
    const int wm = (wid & (MW - 1)) * (MF * 16);
    const int wn = (wid / MW) * (NF * 8);
    const int r = lane >> 2, cq = lane & 3;
    const int nch = K / 16;

    auto issue = [&](int c) {
        float* As = sm + (c % 3) * STG;
        float* Bs = As + BM * 20;
        const int k0 = c * 16;
        #pragma unroll
        for (int i = 0; i < LA; i++) {
            int f = tid + i * 256;
            int m = f >> 2, k4 = (f & 3) << 2;
            cpa16(As + m * 20 + k4, A + (size_t)m * lda + k0 + k4);
        }
        #pragma unroll
        for (int i = 0; i < LB; i++) {
            int f = tid + i * 256;
            int k = f / (BN / 4), n4 = (f % (BN / 4)) << 2;
            cpa16(Bs + k * BNS + n4, B + (size_t)(k0 + k) * ldb + n4);
        }
    };

    issue(0); CPC;
    issue(1); CPC;
    for (int c = 0; c < nch; c++) {
        if (c + 2 < nch) {
            CPW(1);
            __syncthreads();
            issue(c + 2); CPC;
        } else {
            CPW(0);
            __syncthreads();
        }
        const unsigned* As = (const unsigned*)(sm + (c % 3) * STG);
        const unsigned* Bs = As + BM * 20;
        #pragma unroll
        for (int ks = 0; ks < 2; ks++) {
            const int cc = ks * 8 + cq;
            unsigned a[MF][4];
            #pragma unroll
            for (int mf = 0; mf < MF; mf++) {
                const unsigned* p = As + (wm + mf * 16 + r) * 20 + cc;
                a[mf][0] = p[0];
                a[mf][1] = p[8 * 20];
                a[mf][2] = p[4];
                a[mf][3] = p[8 * 20 + 4];
            }
            #pragma unroll
            for (int nf = 0; nf < NF; nf++) {
                const int n = wn + nf * 8 + r;
                unsigned b0 = Bs[cc * BNS + n];
                unsigned b1 = Bs[(cc + 4) * BNS + n];
                #pragma unroll
                for (int mf = 0; mf < MF; mf++) {
                    MMA_TF32(acc[mf][nf], a[mf], b0, b1);
                }
            }
        }
    }
}

#define QKV_SMEM_BYTES  (3 * (128 * 20 + 16 * 136) * 4)   // 56832
#define CTX_SMEM_BYTES  (3 * (256 * 20 + 16 * 72) * 4)    // 75264

// ---------------------------------------------------------------------------
// 1) Fused QKV projections (NN): M=4096, N=1024, K=1024. Grid (8, 32, 3).
//    BM=128, BN=128, warp tile 64x32, 2 CTAs/SM. Writes tf32-rounded values.
// ---------------------------------------------------------------------------
__global__ __launch_bounds__(256, 2) void qkv_gemm(
    const float* __restrict__ bq, const float* __restrict__ bk,
    const float* __restrict__ bv)
{
    extern __shared__ float sm[];
    const float* A; const float* W; const float* bias; float* C;
    if (blockIdx.z == 0)      { A = g_xq; W = g_wq; bias = bq; C = g_q; }
    else if (blockIdx.z == 1) { A = g_xk; W = g_wk; bias = bk; C = g_k; }
    else                      { A = g_xv; W = g_wv; bias = bv; C = g_v; }
    const int bm = blockIdx.y * 128, bn = blockIdx.x * 128;
    float acc[4][4][4] = {};
    gemm_pipe<2, 4, 4, 136>(A + (size_t)bm * DM, DM, W + bn, DM, DM, sm, acc);

    const int lane = threadIdx.x & 31, wid = threadIdx.x >> 5;
    const int wm = (wid & 1) * 64, wn = (wid >> 1) * 32;
    const int r = lane >> 2, cq = lane & 3;
    #pragma unroll
    for (int mf = 0; mf < 4; mf++) {
        #pragma unroll
        for (int nf = 0; nf < 4; nf++) {
            int row = bm + wm + mf * 16 + r;
            int col = bn + wn + nf * 8 + 2 * cq;
            float2 bia = *(const float2*)&bias[col];
            *(float2*)&C[(size_t)row * DM + col] =
                make_float2(f2tf(acc[mf][nf][0] + bia.x), f2tf(acc[mf][nf][1] + bia.y));
            *(float2*)&C[(size_t)(row + 8) * DM + col] =
                make_float2(f2tf(acc[mf][nf][2] + bia.x), f2tf(acc[mf][nf][3] + bia.y));
        }
    }
}

// ---------------------------------------------------------------------------
// 2) Scores (NT): per bh, 128x128 tile, K=64. Grid (8, 8, 64). 2 CTAs/SM.
// ---------------------------------------------------------------------------
#define SCORES_SMEM_BYTES (2 * 128 * 68 * 4)   // 69632

__global__ __launch_bounds__(256, 2) void scores_kernel(
    const void* __restrict__ mask, float* __restrict__ attn_ext, int use_ext)
{
    extern __shared__ float sm[];
    float* Qs = sm;              // [128][68]
    float* Ks = sm + 128 * 68;   // [128][68]
    const int tid = threadIdx.x, lane = tid & 31, wid = tid >> 5;
    const int r = lane >> 2, cq = lane & 3;
    const int bh = blockIdx.z, b = bh >> 4, h = bh & 15;
    const int bi = blockIdx.y * 128, bj = blockIdx.x * 128;
    const float* qb = g_q + (size_t)b * SS * DM + h * DH + (size_t)bi * DM;
    const float* kb = g_k + (size_t)b * SS * DM + h * DH + (size_t)bj * DM;

    #pragma unroll
    for (int i = 0; i < 8; i++) {
        int f = tid + i * 256;
        int m = f >> 4, k4 = (f & 15) << 2;
        cpa16(Qs + m * 68 + k4, qb + (size_t)m * DM + k4);
        cpa16(Ks + m * 68 + k4, kb + (size_t)m * DM + k4);
    }
    CPC; CPW(0);
    __syncthreads();

    const unsigned* Qu = (const unsigned*)Qs;
    const unsigned* Ku = (const unsigned*)Ks;
    const int wm = (wid & 3) * 32, wn = (wid >> 2) * 64;
    float acc[2][8][4] = {};
    #pragma unroll
    for (int kc = 0; kc < 8; kc++) {
        const int cc = kc * 8 + cq;
        unsigned a[2][4];
        #pragma unroll
        for (int mf = 0; mf < 2; mf++) {
            const unsigned* p = Qu + (wm + mf * 16 + r) * 68 + cc;
            a[mf][0] = p[0]; a[mf][1] = p[8 * 68]; a[mf][2] = p[4]; a[mf][3] = p[8 * 68 + 4];
        }
        #pragma unroll
        for (int nf = 0; nf < 8; nf++) {
            const unsigned* p = Ku + (wn + nf * 8 + r) * 68 + cc;
            unsigned b0 = p[0], b1 = p[4];
            #pragma unroll
            for (int mf = 0; mf < 2; mf++) {
                MMA_TF32(acc[mf][nf], a[mf], b0, b1);
            }
        }
    }

    float* attn = use_ext ? attn_ext : g_attn;
    float* outb = attn + (size_t)bh * SS * SS;
    const size_t mbase = (size_t)b * SS * SS;
    const int mi32 = g_mask_is_int32;
    const int* m32 = (const int*)mask;
    const unsigned char* m8 = (const unsigned char*)mask;
    #pragma unroll
    for (int mf = 0; mf < 2; mf++) {
        #pragma unroll
        for (int nf = 0; nf < 8; nf++) {
            int row = bi + wm + mf * 16 + r;
            int col = bj + wn + nf * 8 + 2 * cq;
            #pragma unroll
            for (int half = 0; half < 2; half++) {
                int rr = row + half * 8;
                size_t mi = mbase + (size_t)rr * SS + col;
                bool ma, mb;
                if (mi32) { ma = m32[mi] != 0; mb = m32[mi + 1] != 0; }
                else      { ma = m8[mi]  != 0; mb = m8[mi + 1]  != 0; }
                float v0 = ma ? -1e9f : acc[mf][nf][2 * half + 0] * 0.125f;
                float v1 = mb ? -1e9f : acc[mf][nf][2 * half + 1] * 0.125f;
                *(float2*)&outb[(size_t)rr * SS + col] = make_float2(v0, v1);
            }
        }
    }
}

// ---------------------------------------------------------------------------
// 3) Row softmax over S=1024, in place; writes tf32-rounded P. Grid 65536.
// ---------------------------------------------------------------------------
__global__ __launch_bounds__(256) void softmax_kernel(float* __restrict__ attn_ext, int use_ext) {
    float* attn = use_ext ? attn_ext : g_attn;
    float4* row = (float4*)(attn + (size_t)blockIdx.x * SS);
    const int t = threadIdx.x, lane = t & 31, w = t >> 5;
    __shared__ float sm_[8], ss_[8];

    float4 x = row[t];
    float m = fmaxf(fmaxf(x.x, x.y), fmaxf(x.z, x.w));
    #pragma unroll
    for (int o = 16; o > 0; o >>= 1) m = fmaxf(m, __shfl_xor_sync(0xffffffffu, m, o));
    if (lane == 0) sm_[w] = m;
    __syncthreads();
    float M = sm_[0];
    #pragma unroll
    for (int i = 1; i < 8; i++) M = fmaxf(M, sm_[i]);

    float e0 = __expf(x.x - M), e1 = __expf(x.y - M);
    float e2 = __expf(x.z - M), e3 = __expf(x.w - M);
    float s = e0 + e1 + e2 + e3;
    #pragma unroll
    for (int o = 16; o > 0; o >>= 1) s += __shfl_xor_sync(0xffffffffu, s, o);
    if (lane == 0) ss_[w] = s;
    __syncthreads();
    float S = ss_[0];
    #pragma unroll
    for (int i = 1; i < 8; i++) S += ss_[i];
    float inv = 1.0f / S;
    row[t] = make_float4(f2tf(e0 * inv), f2tf(e1 * inv), f2tf(e2 * inv), f2tf(e3 * inv));
}

// ---------------------------------------------------------------------------
// 4) Context (NN): per bh M=1024, N=64, K=1024. Grid (1, 4, 64).
//    BM=256, BN=64, warp tile 64x32, 2 CTAs/SM. Writes tf32-rounded ctx.
// ---------------------------------------------------------------------------
__global__ __launch_bounds__(256, 2) void context_kernel(const float* __restrict__ attn_ext, int use_ext) {
    extern __shared__ float sm[];
    const int bh = blockIdx.z, b = bh >> 4, h = bh & 15;
    const int bi = blockIdx.y * 256;
    const float* attn = use_ext ? attn_ext : g_attn;
    const float* ab = attn + (size_t)bh * SS * SS + (size_t)bi * SS;
    const float* vb = g_v + (size_t)b * SS * DM + h * DH;
    float acc[4][4][4] = {};
    gemm_pipe<4, 4, 4, 72>(ab, SS, vb, DM, SS, sm, acc);

    const int lane = threadIdx.x & 31, wid = threadIdx.x >> 5;
    const int wm = (wid & 3) * 64, wn = (wid >> 2) * 32;
    const int r = lane >> 2, cq = lane & 3;
    float* cb = g_ctx + (size_t)b * SS * DM + h * DH;
    #pragma unroll
    for (int mf = 0; mf < 4; mf++) {
        #pragma unroll
        for (int nf = 0; nf < 4; nf++) {
            int row = bi + wm + mf * 16 + r;
            int col = wn + nf * 8 + 2 * cq;
            *(float2*)&cb[(size_t)row * DM + col] =
                make_float2(f2tf(acc[mf][nf][0]), f2tf(acc[mf][nf][1]));
            *(float2*)&cb[(size_t)(row + 8) * DM + col] =
                make_float2(f2tf(acc[mf][nf][2]), f2tf(acc[mf][nf][3]));
        }
    }
}

// ---------------------------------------------------------------------------
// 5) Output projection + residual (NN): y = ctx @ Wo + bo + Qin. Grid (8, 32).
// ---------------------------------------------------------------------------
__global__ __launch_bounds__(256, 2) void outproj_kernel(
    const float* __restrict__ bo, const float* __restrict__ Qres)
{
    extern __shared__ float sm[];
    const int bm = blockIdx.y * 128, bn = blockIdx.x * 128;
    float acc[4][4][4] = {};
    gemm_pipe<2, 4, 4, 136>(g_ctx + (size_t)bm * DM, DM, g_wo + bn, DM, DM, sm, acc);

    const int lane = threadIdx.x & 31, wid = threadIdx.x >> 5;
    const int wm = (wid & 1) * 64, wn = (wid >> 1) * 32;
    const int r = lane >> 2, cq = lane & 3;
    #pragma unroll
    for (int mf = 0; mf < 4; mf++) {
        #pragma unroll
        for (int nf = 0; nf < 4; nf++) {
            int row = bm + wm + mf * 16 + r;
            int col = bn + wn + nf * 8 + 2 * cq;
            float2 bia = *(const float2*)&bo[col];
            float2 q0 = *(const float2*)&Qres[(size_t)row * DM + col];
            float2 q1 = *(const float2*)&Qres[(size_t)(row + 8) * DM + col];
            *(float2*)&g_y[(size_t)row * DM + col] =
                make_float2(acc[mf][nf][0] + bia.x + q0.x, acc[mf][nf][1] + bia.y + q0.y);
            *(float2*)&g_y[(size_t)(row + 8) * DM + col] =
                make_float2(acc[mf][nf][2] + bia.x + q1.x, acc[mf][nf][3] + bia.y + q1.y);
        }
    }
}

// ---------------------------------------------------------------------------
// 6) LayerNorm over last dim (1024), biased variance, eps 1e-5. Grid 4096x256.
// ---------------------------------------------------------------------------
__global__ __launch_bounds__(256) void ln_kernel(
    const float* __restrict__ gamma, const float* __restrict__ beta,
    float* __restrict__ out)
{
    const float4* row = (const float4*)(g_y + (size_t)blockIdx.x * DM);
    const int t = threadIdx.x, lane = t & 31, w = t >> 5;
    __shared__ float s1[8], s2[8];
    float4 x = row[t];
    float a = x.x + x.y + x.z + x.w;
    float b = x.x * x.x + x.y * x.y + x.z * x.z + x.w * x.w;
    #pragma unroll
    for (int o = 16; o > 0; o >>= 1) {
        a += __shfl_xor_sync(0xffffffffu, a, o);
        b += __shfl_xor_sync(0xffffffffu, b, o);
    }
    if (lane == 0) { s1[w] = a; s2[w] = b; }
    __syncthreads();
    float A = 0.f, B2 = 0.f;
    #pragma unroll
    for (int i = 0; i < 8; i++) { A += s1[i]; B2 += s2[i]; }
    float mean = A * (1.0f / 1024.0f);
    float var = B2 * (1.0f / 1024.0f) - mean * mean;
    float rstd = rsqrtf(var + 1e-5f);
    float4 g = ((const float4*)gamma)[t];
    float4 be = ((const float4*)beta)[t];
    float4 o4;
    o4.x = (x.x - mean) * rstd * g.x + be.x;
    o4.y = (x.y - mean) * rstd * g.y + be.y;
    o4.z = (x.z - mean) * rstd * g.z + be.z;
    o4.w = (x.w - mean) * rstd * g.w + be.w;
    ((float4*)(out + (size_t)blockIdx.x * DM))[t] = o4;
}

// ---------------------------------------------------------------------------
extern "C" void kernel_launch(void* const* d_in, const int* in_sizes, int n_in,
                              void* d_out, int out_size) {
    const float* Qin   = (const float*)d_in[0];
    const void*  mask  = d_in[3];
    const float* Wq    = (const float*)d_in[4];
    const float* bq    = (const float*)d_in[5];
    const float* Wk    = (const float*)d_in[6];
    const float* bk    = (const float*)d_in[7];
    const float* Wv    = (const float*)d_in[8];
    const float* bv    = (const float*)d_in[9];
    const float* Wo    = (const float*)d_in[10];
    const float* bo    = (const float*)d_in[11];
    const float* gamma = (const float*)d_in[12];
    const float* beta  = (const float*)d_in[13];
    float* out = (float*)d_out;

    const int use_ext = (out_size > OUT_ELEMS) ? 1 : 0;
    float* attn_ext = out + OUT_ELEMS;

    cudaFuncSetAttribute(qkv_gemm, cudaFuncAttributeMaxDynamicSharedMemorySize, QKV_SMEM_BYTES);
    cudaFuncSetAttribute(outproj_kernel, cudaFuncAttributeMaxDynamicSharedMemorySize, QKV_SMEM_BYTES);
    cudaFuncSetAttribute(scores_kernel, cudaFuncAttributeMaxDynamicSharedMemorySize, SCORES_SMEM_BYTES);
    cudaFuncSetAttribute(context_kernel, cudaFuncAttributeMaxDynamicSharedMemorySize, CTX_SMEM_BYTES);

    detect_mask_kernel<<<1, 32>>>((const unsigned*)mask);
    round_inputs_kernel<<<dim3(MROWS * DM / 4 / 256, 1, 3), 256>>>(
        Qin, (const float*)d_in[1], (const float*)d_in[2]);
    round_weights_kernel<<<dim3(DM * DM / 4 / 256, 1, 4), 256>>>(Wq, Wk, Wv, Wo);
    qkv_gemm<<<dim3(8, 32, 3), 256, QKV_SMEM_BYTES>>>(bq, bk, bv);
    scores_kernel<<<dim3(8, 8, 64), 256, SCORES_SMEM_BYTES>>>(mask, attn_ext, use_ext);
    softmax_kernel<<<dim3(BI * NH * SS), 256>>>(attn_ext, use_ext);
    context_kernel<<<dim3(1, 4, 64), 256, CTX_SMEM_BYTES>>>(attn_ext, use_ext);
    outproj_kernel<<<dim3(8, 32), 256, QKV_SMEM_BYTES>>>(bo, Qin);
    ln_kernel<<<dim3(MROWS), 256>>>(gamma, beta, out);
    (void)in_sizes; (void)n_in;
}

// round 11
// speedup vs baseline: 1.1195x; 1.1195x over previous
#include <cuda_runtime.h>

// Problem constants
#define BI 4
#define SS 1024
#define DM 1024
#define NH 16
#define DH 64
#define MROWS (BI * SS)            // 4096
#define OUT_ELEMS (MROWS * DM)     // 4194304
#define ATTN_ELEMS ((size_t)BI * NH * SS * SS)

// Scratch (device globals; allocation inside kernel_launch is forbidden)
__device__ float g_xq[MROWS * DM];   // tf32-rounded Qin
__device__ float g_xk[MROWS * DM];   // tf32-rounded Kin
__device__ float g_xv[MROWS * DM];   // tf32-rounded Vin
__device__ float g_wq[DM * DM];      // tf32-rounded weights
__device__ float g_wk[DM * DM];
__device__ float g_wv[DM * DM];
__device__ float g_wo[DM * DM];
__device__ float g_q[MROWS * DM];    // projections (tf32-rounded values)
__device__ float g_k[MROWS * DM];
__device__ float g_v[MROWS * DM];
__device__ float g_ctx[MROWS * DM];  // tf32-rounded context
__device__ float g_y[MROWS * DM];    // pre-LN (fp32)
__device__ float g_attn[ATTN_ELEMS]; // only used if attn not in d_out
__device__ int   g_mask_is_int32;

// ---------------------------------------------------------------------------
// tf32 + cp.async helpers
// ---------------------------------------------------------------------------
__device__ __forceinline__ float f2tf(float x) {
    unsigned u;
    asm("cvt.rna.tf32.f32 %0, %1;" : "=r"(u) : "f"(x));
    return __uint_as_float(u);
}
__device__ __forceinline__ float4 tf32x4(float4 v) {
    return make_float4(f2tf(v.x), f2tf(v.y), f2tf(v.z), f2tf(v.w));
}
__device__ __forceinline__ void cpa16(const void* smem_dst, const void* gmem_src) {
    unsigned d = (unsigned)__cvta_generic_to_shared(smem_dst);
    asm volatile("cp.async.ca.shared.global [%0], [%1], 16;" :: "r"(d), "l"(gmem_src));
}
#define CPC    asm volatile("cp.async.commit_group;")
#define CPW(n) asm volatile("cp.async.wait_group %0;" :: "n"(n))

#define MMA_TF32(d, a, b0, b1) \
    asm volatile("mma.sync.aligned.m16n8k8.row.col.f32.tf32.tf32.f32 " \
                 "{%0,%1,%2,%3}, {%4,%5,%6,%7}, {%8,%9}, {%0,%1,%2,%3};" \
                 : "+f"(d[0]), "+f"(d[1]), "+f"(d[2]), "+f"(d[3]) \
                 : "r"(a[0]), "r"(a[1]), "r"(a[2]), "r"(a[3]), "r"(b0), "r"(b1))

// ---------------------------------------------------------------------------
// Mask dtype detection: int32 (values 0/1) vs uint8 bytes.
// ---------------------------------------------------------------------------
__global__ void detect_mask_kernel(const unsigned* m) {
    int ok = 1;
    for (int i = threadIdx.x; i < 1024; i += 32)
        if (m[i] > 1u) ok = 0;
    unsigned b = __ballot_sync(0xffffffffu, ok);
    if (threadIdx.x == 0) g_mask_is_int32 = (b == 0xffffffffu) ? 1 : 0;
}

// ---------------------------------------------------------------------------
// Pre-round operands to tf32 once.
// ---------------------------------------------------------------------------
__global__ void round_inputs_kernel(const float* __restrict__ Q,
                                    const float* __restrict__ K,
                                    const float* __restrict__ V) {
    const float* s = blockIdx.z == 0 ? Q : blockIdx.z == 1 ? K : V;
    float* d = blockIdx.z == 0 ? g_xq : blockIdx.z == 1 ? g_xk : g_xv;
    size_t i = (size_t)blockIdx.x * blockDim.x + threadIdx.x;
    ((float4*)d)[i] = tf32x4(((const float4*)s)[i]);
}
__global__ void round_weights_kernel(const float* __restrict__ Wq,
                                     const float* __restrict__ Wk,
                                     const float* __restrict__ Wv,
                                     const float* __restrict__ Wo) {
    const float* s = blockIdx.z == 0 ? Wq : blockIdx.z == 1 ? Wk :
                     blockIdx.z == 2 ? Wv : Wo;
    float* d = blockIdx.z == 0 ? g_wq : blockIdx.z == 1 ? g_wk :
               blockIdx.z == 2 ? g_wv : g_wo;
    size_t i = (size_t)blockIdx.x * blockDim.x + threadIdx.x;
    ((float4*)d)[i] = tf32x4(((const float4*)s)[i]);
}

// ---------------------------------------------------------------------------
// 3-stage cp.async pipelined tf32 GEMM body (operands pre-rounded to tf32).
// 256 threads = 8 warps arranged MW x (8/MW); warp tile = (MF*16) x (NF*8).
// A smem: [m][20] — frag banks (20r + cq) % 32 all-distinct.
// B smem: [k][BNS], BNS % 32 == 8 — frag banks (8cq + r) % 32 all-distinct.
// ---------------------------------------------------------------------------
template<int MW, int MF, int NF, int BNS>
__device__ __forceinline__ void gemm_pipe(
    const float* __restrict__ A, int lda,
    const float* __restrict__ B, int ldb,
    int K, float* __restrict__ sm,
    float (&acc)[MF][NF][4])
{
    constexpr int BM = MW * MF * 16;
    constexpr int BN = (8 / MW) * NF * 8;
    constexpr int STG = BM * 20 + 16 * BNS;
    constexpr int LA = BM / 64;
    constexpr int LB = BN / 64;
    const int tid = threadIdx.x;
    const int lane = tid & 31, wid = tid >> 5;
    const int wm = (wid & (MW - 1)) * (MF * 16);
    const int wn = (wid / MW) * (NF * 8);
    const int r = lane >> 2, cq = lane & 3;
    const int nch = K / 16;

    auto issue = [&](int c) {
        float* As = sm + (c % 3) * STG;
        float* Bs = As + BM * 20;
        const int k0 = c * 16;
        #pragma unroll
        for (int i = 0; i < LA; i++) {
            int f = tid + i * 256;
            int m = f >> 2, k4 = (f & 3) << 2;
            cpa16(As + m * 20 + k4, A + (size_t)m * lda + k0 + k4);
        }
        #pragma unroll
        for (int i = 0; i < LB; i++) {
            int f = tid + i * 256;
            int k = f / (BN / 4), n4 = (f % (BN / 4)) << 2;
            cpa16(Bs + k * BNS + n4, B + (size_t)(k0 + k) * ldb + n4);
        }
    };

    issue(0); CPC;
    issue(1); CPC;
    for (int c = 0; c < nch; c++) {
        if (c + 2 < nch) {
            CPW(1);
            __syncthreads();
            issue(c + 2); CPC;
        } else {
            CPW(0);
            __syncthreads();
        }
        const unsigned* As = (const unsigned*)(sm + (c % 3) * STG);
        const unsigned* Bs = As + BM * 20;
        #pragma unroll
        for (int ks = 0; ks < 2; ks++) {
            const int cc = ks * 8 + cq;
            unsigned a[MF][4];
            #pragma unroll
            for (int mf = 0; mf < MF; mf++) {
                const unsigned* p = As + (wm + mf * 16 + r) * 20 + cc;
                a[mf][0] = p[0];
                a[mf][1] = p[8 * 20];
                a[mf][2] = p[4];
                a[mf][3] = p[8 * 20 + 4];
            }
            #pragma unroll
            for (int nf = 0; nf < NF; nf++) {
                const int n = wn + nf * 8 + r;
                unsigned b0 = Bs[cc * BNS + n];
                unsigned b1 = Bs[(cc + 4) * BNS + n];
                #pragma unroll
                for (int mf = 0; mf < MF; mf++) {
                    MMA_TF32(acc[mf][nf], a[mf], b0, b1);
                }
            }
        }
    }
}

#define QKV_SMEM_BYTES  (3 * (128 * 20 + 16 * 264) * 4)   // 81408
#define CTX_SMEM_BYTES  (3 * (256 * 20 + 16 * 72) * 4)    // 75264

// ---------------------------------------------------------------------------
// 1) Fused QKV projections (NN): M=4096, N=1024, K=1024. Grid (4, 32, 3).
//    BM=128, BN=256, warp tile 64x64 (R7 config, best measured).
// ---------------------------------------------------------------------------
__global__ __launch_bounds__(256) void qkv_gemm(
    const float* __restrict__ bq, const float* __restrict__ bk,
    const float* __restrict__ bv)
{
    extern __shared__ float sm[];
    const float* A; const float* W; const float* bias; float* C;
    if (blockIdx.z == 0)      { A = g_xq; W = g_wq; bias = bq; C = g_q; }
    else if (blockIdx.z == 1) { A = g_xk; W = g_wk; bias = bk; C = g_k; }
    else                      { A = g_xv; W = g_wv; bias = bv; C = g_v; }
    const int bm = blockIdx.y * 128, bn = blockIdx.x * 256;
    float acc[4][8][4] = {};
    gemm_pipe<2, 4, 8, 264>(A + (size_t)bm * DM, DM, W + bn, DM, DM, sm, acc);

    const int lane = threadIdx.x & 31, wid = threadIdx.x >> 5;
    const int wm = (wid & 1) * 64, wn = (wid >> 1) * 64;
    const int r = lane >> 2, cq = lane & 3;
    #pragma unroll
    for (int mf = 0; mf < 4; mf++) {
        #pragma unroll
        for (int nf = 0; nf < 8; nf++) {
            int row = bm + wm + mf * 16 + r;
            int col = bn + wn + nf * 8 + 2 * cq;
            float2 bia = *(const float2*)&bias[col];
            *(float2*)&C[(size_t)row * DM + col] =
                make_float2(f2tf(acc[mf][nf][0] + bia.x), f2tf(acc[mf][nf][1] + bia.y));
            *(float2*)&C[(size_t)(row + 8) * DM + col] =
                make_float2(f2tf(acc[mf][nf][2] + bia.x), f2tf(acc[mf][nf][3] + bia.y));
        }
    }
}

// ---------------------------------------------------------------------------
// 2) FUSED scores + mask + softmax. Block = 32 query rows x full S for one
// (b,h). Grid (32, 64), 256 threads. Scores stay in smem (32x1028 fp32);
// exact two-sweep softmax; attn written to gmem ONCE (tf32-rounded).
// K tiles (128x64 floats = 2048 float4 = 8/thread) stream via 2-stage ring.
// ---------------------------------------------------------------------------
#define FUS_STRIDE 1028
#define FUS_SMEM_BYTES ((32 * FUS_STRIDE + 32 * 68 + 2 * 128 * 68) * 4)  // 209920

__global__ __launch_bounds__(256) void scores_softmax_kernel(
    const void* __restrict__ mask, float* __restrict__ attn_ext, int use_ext)
{
    extern __shared__ float sm[];
    float* Ss = sm;                          // [32][1028]
    float* Qs = Ss + 32 * FUS_STRIDE;        // [32][68]
    float* Ks = Qs + 32 * 68;                // 2 stages x [128][68]
    const int tid = threadIdx.x, lane = tid & 31, wid = tid >> 5;
    const int r = lane >> 2, cq = lane & 3;
    const int bh = blockIdx.y, b = bh >> 4, h = bh & 15;
    const int i0 = blockIdx.x * 32;
    const float* qb = g_q + (size_t)b * SS * DM + h * DH + (size_t)i0 * DM;
    const float* kb = g_k + (size_t)b * SS * DM + h * DH;

    // Q tile 32x64 floats = 512 float4 = 2 per thread
    #pragma unroll
    for (int i = 0; i < 2; i++) {
        int f = tid + i * 256;
        int m = f >> 4, k4 = (f & 15) << 2;
        cpa16(Qs + m * 68 + k4, qb + (size_t)m * DM + k4);
    }
    // K tile 128x64 floats = 2048 float4 = 8 per thread
    auto issueK = [&](int jt) {
        float* Kst = Ks + (jt & 1) * (128 * 68);
        const float* kbj = kb + (size_t)jt * 128 * DM;
        #pragma unroll
        for (int i = 0; i < 8; i++) {
            int f = tid + i * 256;
            int m = f >> 4, k4 = (f & 15) << 2;
            cpa16(Kst + m * 68 + k4, kbj + (size_t)m * DM + k4);
        }
    };
    issueK(0); CPC;   // groups Q tile with K stage 0

    const int wm = (wid & 1) * 16, wn = (wid >> 1) * 32;
    for (int jt = 0; jt < 8; jt++) {
        if (jt < 7) { issueK(jt + 1); CPC; CPW(1); }
        else        { CPW(0); }
        __syncthreads();   // stage jt visible to all
        const unsigned* Qu = (const unsigned*)Qs;
        const unsigned* Ku = (const unsigned*)(Ks + (jt & 1) * (128 * 68));
        float acc[4][4] = {};
        #pragma unroll
        for (int kc = 0; kc < 8; kc++) {
            const int cc = kc * 8 + cq;
            unsigned a[4];
            const unsigned* pa = Qu + (wm + r) * 68 + cc;
            a[0] = pa[0]; a[1] = pa[8 * 68]; a[2] = pa[4]; a[3] = pa[8 * 68 + 4];
            #pragma unroll
            for (int nf = 0; nf < 4; nf++) {
                const unsigned* pb = Ku + (wn + nf * 8 + r) * 68 + cc;
                MMA_TF32(acc[nf], a, pb[0], pb[4]);
            }
        }
        #pragma unroll
        for (int nf = 0; nf < 4; nf++) {
            int col = jt * 128 + wn + nf * 8 + 2 * cq;
            *(float2*)&Ss[(wm + r) * FUS_STRIDE + col] =
                make_float2(acc[nf][0], acc[nf][1]);
            *(float2*)&Ss[(wm + r + 8) * FUS_STRIDE + col] =
                make_float2(acc[nf][2], acc[nf][3]);
        }
        __syncthreads();   // reads of stage jt complete before overwrite
    }

    // Softmax: warp w owns rows 4w..4w+3. Mask+scale+rowmax, exp+sum, write.
    const int mi32 = g_mask_is_int32;
    const int* m32 = (const int*)mask;
    const unsigned char* m8 = (const unsigned char*)mask;
    float* attn = use_ext ? attn_ext : g_attn;
    #pragma unroll
    for (int rl = 0; rl < 4; rl++) {
        int row = wid * 4 + rl;
        size_t mbase = (size_t)b * SS * SS + (size_t)(i0 + row) * SS;
        float mx = -3.4e38f;
        #pragma unroll
        for (int it = 0; it < 8; it++) {
            int c0 = (it * 32 + lane) * 4;
            float4 s4 = *(float4*)&Ss[row * FUS_STRIDE + c0];
            int mk0, mk1, mk2, mk3;
            if (mi32) {
                int4 mk = *(const int4*)(m32 + mbase + c0);
                mk0 = mk.x; mk1 = mk.y; mk2 = mk.z; mk3 = mk.w;
            } else {
                uchar4 u = *(const uchar4*)(m8 + mbase + c0);
                mk0 = u.x; mk1 = u.y; mk2 = u.z; mk3 = u.w;
            }
            s4.x = mk0 ? -1e9f : s4.x * 0.125f;
            s4.y = mk1 ? -1e9f : s4.y * 0.125f;
            s4.z = mk2 ? -1e9f : s4.z * 0.125f;
            s4.w = mk3 ? -1e9f : s4.w * 0.125f;
            *(float4*)&Ss[row * FUS_STRIDE + c0] = s4;
            mx = fmaxf(mx, fmaxf(fmaxf(s4.x, s4.y), fmaxf(s4.z, s4.w)));
        }
        #pragma unroll
        for (int o = 16; o; o >>= 1) mx = fmaxf(mx, __shfl_xor_sync(0xffffffffu, mx, o));
        float M = __shfl_sync(0xffffffffu, mx, 0);

        float s = 0.f;
        #pragma unroll
        for (int it = 0; it < 8; it++) {
            int c0 = (it * 32 + lane) * 4;
            float4 v = *(float4*)&Ss[row * FUS_STRIDE + c0];
            v.x = __expf(v.x - M); v.y = __expf(v.y - M);
            v.z = __expf(v.z - M); v.w = __expf(v.w - M);
            *(float4*)&Ss[row * FUS_STRIDE + c0] = v;
            s += v.x + v.y + v.z + v.w;
        }
        #pragma unroll
        for (int o = 16; o; o >>= 1) s += __shfl_xor_sync(0xffffffffu, s, o);
        float inv = 1.0f / s;

        size_t abase = (size_t)bh * SS * SS + (size_t)(i0 + row) * SS;
        #pragma unroll
        for (int it = 0; it < 8; it++) {
            int c0 = (it * 32 + lane) * 4;
            float4 v = *(float4*)&Ss[row * FUS_STRIDE + c0];
            *(float4*)&attn[abase + c0] =
                make_float4(f2tf(v.x * inv), f2tf(v.y * inv),
                            f2tf(v.z * inv), f2tf(v.w * inv));
        }
    }
}

// ---------------------------------------------------------------------------
// 3) Context (NN): per bh M=1024, N=64, K=1024. Grid (1, 4, 64). (R7 verbatim)
// ---------------------------------------------------------------------------
__global__ __launch_bounds__(256) void context_kernel(const float* __restrict__ attn_ext, int use_ext) {
    extern __shared__ float sm[];
    const int bh = blockIdx.z, b = bh >> 4, h = bh & 15;
    const int bi = blockIdx.y * 256;
    const float* attn = use_ext ? attn_ext : g_attn;
    const float* ab = attn + (size_t)bh * SS * SS + (size_t)bi * SS;
    const float* vb = g_v + (size_t)b * SS * DM + h * DH;
    float acc[4][4][4] = {};
    gemm_pipe<4, 4, 4, 72>(ab, SS, vb, DM, SS, sm, acc);

    const int lane = threadIdx.x & 31, wid = threadIdx.x >> 5;
    const int wm = (wid & 3) * 64, wn = (wid >> 2) * 32;
    const int r = lane >> 2, cq = lane & 3;
    float* cb = g_ctx + (size_t)b * SS * DM + h * DH;
    #pragma unroll
    for (int mf = 0; mf < 4; mf++) {
        #pragma unroll
        for (int nf = 0; nf < 4; nf++) {
            int row = bi + wm + mf * 16 + r;
            int col = wn + nf * 8 + 2 * cq;
            *(float2*)&cb[(size_t)row * DM + col] =
                make_float2(f2tf(acc[mf][nf][0]), f2tf(acc[mf][nf][1]));
            *(float2*)&cb[(size_t)(row + 8) * DM + col] =
                make_float2(f2tf(acc[mf][nf][2]), f2tf(acc[mf][nf][3]));
        }
    }
}

// ---------------------------------------------------------------------------
// 4) Output projection + residual (NN): y = ctx @ Wo + bo + Qin. Grid (4, 32).
// ---------------------------------------------------------------------------
__global__ __launch_bounds__(256) void outproj_kernel(
    const float* __restrict__ bo, const float* __restrict__ Qres)
{
    extern __shared__ float sm[];
    const int bm = blockIdx.y * 128, bn = blockIdx.x * 256;
    float acc[4][8][4] = {};
    gemm_pipe<2, 4, 8, 264>(g_ctx + (size_t)bm * DM, DM, g_wo + bn, DM, DM, sm, acc);

    const int lane = threadIdx.x & 31, wid = threadIdx.x >> 5;
    const int wm = (wid & 1) * 64, wn = (wid >> 1) * 64;
    const int r = lane >> 2, cq = lane & 3;
    #pragma unroll
    for (int mf = 0; mf < 4; mf++) {
        #pragma unroll
        for (int nf = 0; nf < 8; nf++) {
            int row = bm + wm + mf * 16 + r;
            int col = bn + wn + nf * 8 + 2 * cq;
            float2 bia = *(const float2*)&bo[col];
            float2 q0 = *(const float2*)&Qres[(size_t)row * DM + col];
            float2 q1 = *(const float2*)&Qres[(size_t)(row + 8) * DM + col];
            *(float2*)&g_y[(size_t)row * DM + col] =
                make_float2(acc[mf][nf][0] + bia.x + q0.x, acc[mf][nf][1] + bia.y + q0.y);
            *(float2*)&g_y[(size_t)(row + 8) * DM + col] =
                make_float2(acc[mf][nf][2] + bia.x + q1.x, acc[mf][nf][3] + bia.y + q1.y);
        }
    }
}

// ---------------------------------------------------------------------------
// 5) LayerNorm over last dim (1024), biased variance, eps 1e-5. Grid 4096x256.
// ---------------------------------------------------------------------------
__global__ __launch_bounds__(256) void ln_kernel(
    const float* __restrict__ gamma, const float* __restrict__ beta,
    float* __restrict__ out)
{
    const float4* row = (const float4*)(g_y + (size_t)blockIdx.x * DM);
    const int t = threadIdx.x, lane = t & 31, w = t >> 5;
    __shared__ float s1[8], s2[8];
    float4 x = row[t];
    float a = x.x + x.y + x.z + x.w;
    float b = x.x * x.x + x.y * x.y + x.z * x.z + x.w * x.w;
    #pragma unroll
    for (int o = 16; o > 0; o >>= 1) {
        a += __shfl_xor_sync(0xffffffffu, a, o);
        b += __shfl_xor_sync(0xffffffffu, b, o);
    }
    if (lane == 0) { s1[w] = a; s2[w] = b; }
    __syncthreads();
    float A = 0.f, B2 = 0.f;
    #pragma unroll
    for (int i = 0; i < 8; i++) { A += s1[i]; B2 += s2[i]; }
    float mean = A * (1.0f / 1024.0f);
    float var = B2 * (1.0f / 1024.0f) - mean * mean;
    float rstd = rsqrtf(var + 1e-5f);
    float4 g = ((const float4*)gamma)[t];
    float4 be = ((const float4*)beta)[t];
    float4 o4;
    o4.x = (x.x - mean) * rstd * g.x + be.x;
    o4.y = (x.y - mean) * rstd * g.y + be.y;
    o4.z = (x.z - mean) * rstd * g.z + be.z;
    o4.w = (x.w - mean) * rstd * g.w + be.w;
    ((float4*)(out + (size_t)blockIdx.x * DM))[t] = o4;
}

// ---------------------------------------------------------------------------
extern "C" void kernel_launch(void* const* d_in, const int* in_sizes, int n_in,
                              void* d_out, int out_size) {
    const float* Qin   = (const float*)d_in[0];
    const void*  mask  = d_in[3];
    const float* Wq    = (const float*)d_in[4];
    const float* bq    = (const float*)d_in[5];
    const float* Wk    = (const float*)d_in[6];
    const float* bk    = (const float*)d_in[7];
    const float* Wv    = (const float*)d_in[8];
    const float* bv    = (const float*)d_in[9];
    const float* Wo    = (const float*)d_in[10];
    const float* bo    = (const float*)d_in[11];
    const float* gamma = (const float*)d_in[12];
    const float* beta  = (const float*)d_in[13];
    float* out = (float*)d_out;

    const int use_ext = (out_size > OUT_ELEMS) ? 1 : 0;
    float* attn_ext = out + OUT_ELEMS;

    cudaFuncSetAttribute(qkv_gemm, cudaFuncAttributeMaxDynamicSharedMemorySize, QKV_SMEM_BYTES);
    cudaFuncSetAttribute(outproj_kernel, cudaFuncAttributeMaxDynamicSharedMemorySize, QKV_SMEM_BYTES);
    cudaFuncSetAttribute(scores_softmax_kernel, cudaFuncAttributeMaxDynamicSharedMemorySize, FUS_SMEM_BYTES);
    cudaFuncSetAttribute(context_kernel, cudaFuncAttributeMaxDynamicSharedMemorySize, CTX_SMEM_BYTES);

    detect_mask_kernel<<<1, 32>>>((const unsigned*)mask);
    round_inputs_kernel<<<dim3(MROWS * DM / 4 / 256, 1, 3), 256>>>(
        Qin, (const float*)d_in[1], (const float*)d_in[2]);
    round_weights_kernel<<<dim3(DM * DM / 4 / 256, 1, 4), 256>>>(Wq, Wk, Wv, Wo);
    qkv_gemm<<<dim3(4, 32, 3), 256, QKV_SMEM_BYTES>>>(bq, bk, bv);
    scores_softmax_kernel<<<dim3(32, 64), 256, FUS_SMEM_BYTES>>>(mask, attn_ext, use_ext);
    context_kernel<<<dim3(1, 4, 64), 256, CTX_SMEM_BYTES>>>(attn_ext, use_ext);
    outproj_kernel<<<dim3(4, 32), 256, QKV_SMEM_BYTES>>>(bo, Qin);
    ln_kernel<<<dim3(MROWS), 256>>>(gamma, beta, out);
    (void)in_sizes; (void)n_in;
}

// round 12
// speedup vs baseline: 1.1701x; 1.0452x over previous
#include <cuda_runtime.h>

// Problem constants
#define BI 4
#define SS 1024
#define DM 1024
#define NH 16
#define DH 64
#define MROWS (BI * SS)            // 4096
#define OUT_ELEMS (MROWS * DM)     // 4194304
#define ATTN_ELEMS ((size_t)BI * NH * SS * SS)

// Scratch (device globals; allocation inside kernel_launch is forbidden)
__device__ float g_xq[MROWS * DM];   // tf32-rounded Qin
__device__ float g_xk[MROWS * DM];   // tf32-rounded Kin
__device__ float g_xv[MROWS * DM];   // tf32-rounded Vin
__device__ float g_wq[DM * DM];      // tf32-rounded weights
__device__ float g_wk[DM * DM];
__device__ float g_wv[DM * DM];
__device__ float g_wo[DM * DM];
__device__ float g_q[MROWS * DM];    // projections (tf32-rounded values)
__device__ float g_k[MROWS * DM];
__device__ float g_v[MROWS * DM];
__device__ float g_ctx[MROWS * DM];  // tf32-rounded context
__device__ float g_y[MROWS * DM];    // pre-LN (fp32)
__device__ float g_attn[ATTN_ELEMS]; // only used if attn not in d_out
__device__ int   g_mask_is_int32;

// ---------------------------------------------------------------------------
// tf32 + cp.async helpers
// ---------------------------------------------------------------------------
__device__ __forceinline__ float f2tf(float x) {
    unsigned u;
    asm("cvt.rna.tf32.f32 %0, %1;" : "=r"(u) : "f"(x));
    return __uint_as_float(u);
}
__device__ __forceinline__ float4 tf32x4(float4 v) {
    return make_float4(f2tf(v.x), f2tf(v.y), f2tf(v.z), f2tf(v.w));
}
__device__ __forceinline__ void cpa16(const void* smem_dst, const void* gmem_src) {
    unsigned d = (unsigned)__cvta_generic_to_shared(smem_dst);
    asm volatile("cp.async.ca.shared.global [%0], [%1], 16;" :: "r"(d), "l"(gmem_src));
}
#define CPC    asm volatile("cp.async.commit_group;")
#define CPW(n) asm volatile("cp.async.wait_group %0;" :: "n"(n))

#define MMA_TF32(d, a, b0, b1) \
    asm volatile("mma.sync.aligned.m16n8k8.row.col.f32.tf32.tf32.f32 " \
                 "{%0,%1,%2,%3}, {%4,%5,%6,%7}, {%8,%9}, {%0,%1,%2,%3};" \
                 : "+f"(d[0]), "+f"(d[1]), "+f"(d[2]), "+f"(d[3]) \
                 : "r"(a[0]), "r"(a[1]), "r"(a[2]), "r"(a[3]), "r"(b0), "r"(b1))

// ---------------------------------------------------------------------------
// Mask dtype detection: int32 (values 0/1) vs uint8 bytes.
// ---------------------------------------------------------------------------
__global__ void detect_mask_kernel(const unsigned* m) {
    int ok = 1;
    for (int i = threadIdx.x; i < 1024; i += 32)
        if (m[i] > 1u) ok = 0;
    unsigned b = __ballot_sync(0xffffffffu, ok);
    if (threadIdx.x == 0) g_mask_is_int32 = (b == 0xffffffffu) ? 1 : 0;
}

// ---------------------------------------------------------------------------
// Pre-round operands to tf32 once.
// ---------------------------------------------------------------------------
__global__ void round_inputs_kernel(const float* __restrict__ Q,
                                    const float* __restrict__ K,
                                    const float* __restrict__ V) {
    const float* s = blockIdx.z == 0 ? Q : blockIdx.z == 1 ? K : V;
    float* d = blockIdx.z == 0 ? g_xq : blockIdx.z == 1 ? g_xk : g_xv;
    size_t i = (size_t)blockIdx.x * blockDim.x + threadIdx.x;
    ((float4*)d)[i] = tf32x4(((const float4*)s)[i]);
}
__global__ void round_weights_kernel(const float* __restrict__ Wq,
                                     const float* __restrict__ Wk,
                                     const float* __restrict__ Wv,
                                     const float* __restrict__ Wo) {
    const float* s = blockIdx.z == 0 ? Wq : blockIdx.z == 1 ? Wk :
                     blockIdx.z == 2 ? Wv : Wo;
    float* d = blockIdx.z == 0 ? g_wq : blockIdx.z == 1 ? g_wk :
               blockIdx.z == 2 ? g_wv : g_wo;
    size_t i = (size_t)blockIdx.x * blockDim.x + threadIdx.x;
    ((float4*)d)[i] = tf32x4(((const float4*)s)[i]);
}

// ---------------------------------------------------------------------------
// 3-stage cp.async pipelined tf32 GEMM body (operands pre-rounded to tf32).
// NT threads = NT/32 warps arranged MW x (NT/32/MW); warp tile (MF*16)x(NF*8).
// A smem: [m][20] — frag banks (20r + cq) % 32 all-distinct.
// B smem: [k][BNS], BNS % 32 == 8 — frag banks (8cq + r) % 32 all-distinct.
// ---------------------------------------------------------------------------
template<int NT, int MW, int MF, int NF, int BNS>
__device__ __forceinline__ void gemm_pipe(
    const float* __restrict__ A, int lda,
    const float* __restrict__ B, int ldb,
    int K, float* __restrict__ sm,
    float (&acc)[MF][NF][4])
{
    constexpr int NWARP = NT / 32;
    constexpr int BM = MW * MF * 16;
    constexpr int BN = (NWARP / MW) * NF * 8;
    constexpr int STG = BM * 20 + 16 * BNS;
    constexpr int LA = BM * 4 / NT;
    constexpr int LB = BN * 4 / NT;
    const int tid = threadIdx.x;
    const int lane = tid & 31, wid = tid >> 5;
    const int wm = (wid & (MW - 1)) * (MF * 16);
    const int wn = (wid / MW) * (NF * 8);
    const int r = lane >> 2, cq = lane & 3;
    const int nch = K / 16;

    auto issue = [&](int c) {
        float* As = sm + (c % 3) * STG;
        float* Bs = As + BM * 20;
        const int k0 = c * 16;
        #pragma unroll
        for (int i = 0; i < LA; i++) {
            int f = tid + i * NT;
            int m = f >> 2, k4 = (f & 3) << 2;
            cpa16(As + m * 20 + k4, A + (size_t)m * lda + k0 + k4);
        }
        #pragma unroll
        for (int i = 0; i < LB; i++) {
            int f = tid + i * NT;
            int k = f / (BN / 4), n4 = (f % (BN / 4)) << 2;
            cpa16(Bs + k * BNS + n4, B + (size_t)(k0 + k) * ldb + n4);
        }
    };

    issue(0); CPC;
    issue(1); CPC;
    for (int c = 0; c < nch; c++) {
        if (c + 2 < nch) {
            CPW(1);
            __syncthreads();
            issue(c + 2); CPC;
        } else {
            CPW(0);
            __syncthreads();
        }
        const unsigned* As = (const unsigned*)(sm + (c % 3) * STG);
        const unsigned* Bs = As + BM * 20;
        #pragma unroll
        for (int ks = 0; ks < 2; ks++) {
            const int cc = ks * 8 + cq;
            unsigned a[MF][4];
            #pragma unroll
            for (int mf = 0; mf < MF; mf++) {
                const unsigned* p = As + (wm + mf * 16 + r) * 20 + cc;
                a[mf][0] = p[0];
                a[mf][1] = p[8 * 20];
                a[mf][2] = p[4];
                a[mf][3] = p[8 * 20 + 4];
            }
            #pragma unroll
            for (int nf = 0; nf < NF; nf++) {
                const int n = wn + nf * 8 + r;
                unsigned b0 = Bs[cc * BNS + n];
                unsigned b1 = Bs[(cc + 4) * BNS + n];
                #pragma unroll
                for (int mf = 0; mf < MF; mf++) {
                    MMA_TF32(acc[mf][nf], a[mf], b0, b1);
                }
            }
        }
    }
}

#define QKV_SMEM_BYTES  (3 * (128 * 20 + 16 * 136) * 4)   // 56832 (2 CTAs/SM)
#define CTX_SMEM_BYTES  (3 * (256 * 20 + 16 * 72) * 4)    // 75264

// ---------------------------------------------------------------------------
// 1) Fused QKV projections (NN): M=4096, N=1024, K=1024. Grid (8, 32, 3).
//    128 threads = 4 warps of 64x64; BM=128, BN=128; 2 CTAs/SM (decoupled
//    barriers — same warp tile & smem intensity as R7's best config).
// ---------------------------------------------------------------------------
__global__ __launch_bounds__(128, 2) void qkv_gemm(
    const float* __restrict__ bq, const float* __restrict__ bk,
    const float* __restrict__ bv)
{
    extern __shared__ float sm[];
    const float* A; const float* W; const float* bias; float* C;
    if (blockIdx.z == 0)      { A = g_xq; W = g_wq; bias = bq; C = g_q; }
    else if (blockIdx.z == 1) { A = g_xk; W = g_wk; bias = bk; C = g_k; }
    else                      { A = g_xv; W = g_wv; bias = bv; C = g_v; }
    const int bm = blockIdx.y * 128, bn = blockIdx.x * 128;
    float acc[4][8][4] = {};
    gemm_pipe<128, 2, 4, 8, 136>(A + (size_t)bm * DM, DM, W + bn, DM, DM, sm, acc);

    const int lane = threadIdx.x & 31, wid = threadIdx.x >> 5;
    const int wm = (wid & 1) * 64, wn = (wid >> 1) * 64;
    const int r = lane >> 2, cq = lane & 3;
    #pragma unroll
    for (int mf = 0; mf < 4; mf++) {
        #pragma unroll
        for (int nf = 0; nf < 8; nf++) {
            int row = bm + wm + mf * 16 + r;
            int col = bn + wn + nf * 8 + 2 * cq;
            float2 bia = *(const float2*)&bias[col];
            *(float2*)&C[(size_t)row * DM + col] =
                make_float2(f2tf(acc[mf][nf][0] + bia.x), f2tf(acc[mf][nf][1] + bia.y));
            *(float2*)&C[(size_t)(row + 8) * DM + col] =
                make_float2(f2tf(acc[mf][nf][2] + bia.x), f2tf(acc[mf][nf][3] + bia.y));
        }
    }
}

// ---------------------------------------------------------------------------
// 2) FUSED scores + mask + softmax. (R11 verbatim — proven.)
// ---------------------------------------------------------------------------
#define FUS_STRIDE 1028
#define FUS_SMEM_BYTES ((32 * FUS_STRIDE + 32 * 68 + 2 * 128 * 68) * 4)  // 209920

__global__ __launch_bounds__(256) void scores_softmax_kernel(
    const void* __restrict__ mask, float* __restrict__ attn_ext, int use_ext)
{
    extern __shared__ float sm[];
    float* Ss = sm;                          // [32][1028]
    float* Qs = Ss + 32 * FUS_STRIDE;        // [32][68]
    float* Ks = Qs + 32 * 68;                // 2 stages x [128][68]
    const int tid = threadIdx.x, lane = tid & 31, wid = tid >> 5;
    const int r = lane >> 2, cq = lane & 3;
    const int bh = blockIdx.y, b = bh >> 4, h = bh & 15;
    const int i0 = blockIdx.x * 32;
    const float* qb = g_q + (size_t)b * SS * DM + h * DH + (size_t)i0 * DM;
    const float* kb = g_k + (size_t)b * SS * DM + h * DH;

    #pragma unroll
    for (int i = 0; i < 2; i++) {
        int f = tid + i * 256;
        int m = f >> 4, k4 = (f & 15) << 2;
        cpa16(Qs + m * 68 + k4, qb + (size_t)m * DM + k4);
    }
    auto issueK = [&](int jt) {
        float* Kst = Ks + (jt & 1) * (128 * 68);
        const float* kbj = kb + (size_t)jt * 128 * DM;
        #pragma unroll
        for (int i = 0; i < 8; i++) {
            int f = tid + i * 256;
            int m = f >> 4, k4 = (f & 15) << 2;
            cpa16(Kst + m * 68 + k4, kbj + (size_t)m * DM + k4);
        }
    };
    issueK(0); CPC;

    const int wm = (wid & 1) * 16, wn = (wid >> 1) * 32;
    for (int jt = 0; jt < 8; jt++) {
        if (jt < 7) { issueK(jt + 1); CPC; CPW(1); }
        else        { CPW(0); }
        __syncthreads();
        const unsigned* Qu = (const unsigned*)Qs;
        const unsigned* Ku = (const unsigned*)(Ks + (jt & 1) * (128 * 68));
        float acc[4][4] = {};
        #pragma unroll
        for (int kc = 0; kc < 8; kc++) {
            const int cc = kc * 8 + cq;
            unsigned a[4];
            const unsigned* pa = Qu + (wm + r) * 68 + cc;
            a[0] = pa[0]; a[1] = pa[8 * 68]; a[2] = pa[4]; a[3] = pa[8 * 68 + 4];
            #pragma unroll
            for (int nf = 0; nf < 4; nf++) {
                const unsigned* pb = Ku + (wn + nf * 8 + r) * 68 + cc;
                MMA_TF32(acc[nf], a, pb[0], pb[4]);
            }
        }
        #pragma unroll
        for (int nf = 0; nf < 4; nf++) {
            int col = jt * 128 + wn + nf * 8 + 2 * cq;
            *(float2*)&Ss[(wm + r) * FUS_STRIDE + col] =
                make_float2(acc[nf][0], acc[nf][1]);
            *(float2*)&Ss[(wm + r + 8) * FUS_STRIDE + col] =
                make_float2(acc[nf][2], acc[nf][3]);
        }
        __syncthreads();
    }

    const int mi32 = g_mask_is_int32;
    const int* m32 = (const int*)mask;
    const unsigned char* m8 = (const unsigned char*)mask;
    float* attn = use_ext ? attn_ext : g_attn;
    #pragma unroll
    for (int rl = 0; rl < 4; rl++) {
        int row = wid * 4 + rl;
        size_t mbase = (size_t)b * SS * SS + (size_t)(i0 + row) * SS;
        float mx = -3.4e38f;
        #pragma unroll
        for (int it = 0; it < 8; it++) {
            int c0 = (it * 32 + lane) * 4;
            float4 s4 = *(float4*)&Ss[row * FUS_STRIDE + c0];
            int mk0, mk1, mk2, mk3;
            if (mi32) {
                int4 mk = *(const int4*)(m32 + mbase + c0);
                mk0 = mk.x; mk1 = mk.y; mk2 = mk.z; mk3 = mk.w;
            } else {
                uchar4 u = *(const uchar4*)(m8 + mbase + c0);
                mk0 = u.x; mk1 = u.y; mk2 = u.z; mk3 = u.w;
            }
            s4.x = mk0 ? -1e9f : s4.x * 0.125f;
            s4.y = mk1 ? -1e9f : s4.y * 0.125f;
            s4.z = mk2 ? -1e9f : s4.z * 0.125f;
            s4.w = mk3 ? -1e9f : s4.w * 0.125f;
            *(float4*)&Ss[row * FUS_STRIDE + c0] = s4;
            mx = fmaxf(mx, fmaxf(fmaxf(s4.x, s4.y), fmaxf(s4.z, s4.w)));
        }
        #pragma unroll
        for (int o = 16; o; o >>= 1) mx = fmaxf(mx, __shfl_xor_sync(0xffffffffu, mx, o));
        float M = __shfl_sync(0xffffffffu, mx, 0);

        float s = 0.f;
        #pragma unroll
        for (int it = 0; it < 8; it++) {
            int c0 = (it * 32 + lane) * 4;
            float4 v = *(float4*)&Ss[row * FUS_STRIDE + c0];
            v.x = __expf(v.x - M); v.y = __expf(v.y - M);
            v.z = __expf(v.z - M); v.w = __expf(v.w - M);
            *(float4*)&Ss[row * FUS_STRIDE + c0] = v;
            s += v.x + v.y + v.z + v.w;
        }
        #pragma unroll
        for (int o = 16; o; o >>= 1) s += __shfl_xor_sync(0xffffffffu, s, o);
        float inv = 1.0f / s;

        size_t abase = (size_t)bh * SS * SS + (size_t)(i0 + row) * SS;
        #pragma unroll
        for (int it = 0; it < 8; it++) {
            int c0 = (it * 32 + lane) * 4;
            float4 v = *(float4*)&Ss[row * FUS_STRIDE + c0];
            *(float4*)&attn[abase + c0] =
                make_float4(f2tf(v.x * inv), f2tf(v.y * inv),
                            f2tf(v.z * inv), f2tf(v.w * inv));
        }
    }
}

// ---------------------------------------------------------------------------
// 3) Context (NN): per bh M=1024, N=64, K=1024. Grid (1, 4, 64). (R7 verbatim)
// ---------------------------------------------------------------------------
__global__ __launch_bounds__(256) void context_kernel(const float* __restrict__ attn_ext, int use_ext) {
    extern __shared__ float sm[];
    const int bh = blockIdx.z, b = bh >> 4, h = bh & 15;
    const int bi = blockIdx.y * 256;
    const float* attn = use_ext ? attn_ext : g_attn;
    const float* ab = attn + (size_t)bh * SS * SS + (size_t)bi * SS;
    const float* vb = g_v + (size_t)b * SS * DM + h * DH;
    float acc[4][4][4] = {};
    gemm_pipe<256, 4, 4, 4, 72>(ab, SS, vb, DM, SS, sm, acc);

    const int lane = threadIdx.x & 31, wid = threadIdx.x >> 5;
    const int wm = (wid & 3) * 64, wn = (wid >> 2) * 32;
    const int r = lane >> 2, cq = lane & 3;
    float* cb = g_ctx + (size_t)b * SS * DM + h * DH;
    #pragma unroll
    for (int mf = 0; mf < 4; mf++) {
        #pragma unroll
        for (int nf = 0; nf < 4; nf++) {
            int row = bi + wm + mf * 16 + r;
            int col = wn + nf * 8 + 2 * cq;
            *(float2*)&cb[(size_t)row * DM + col] =
                make_float2(f2tf(acc[mf][nf][0]), f2tf(acc[mf][nf][1]));
            *(float2*)&cb[(size_t)(row + 8) * DM + col] =
                make_float2(f2tf(acc[mf][nf][2]), f2tf(acc[mf][nf][3]));
        }
    }
}

// ---------------------------------------------------------------------------
// 4) Output projection + residual (NN). Grid (8, 32), 128 thr, 2 CTAs/SM.
// ---------------------------------------------------------------------------
__global__ __launch_bounds__(128, 2) void outproj_kernel(
    const float* __restrict__ bo, const float* __restrict__ Qres)
{
    extern __shared__ float sm[];
    const int bm = blockIdx.y * 128, bn = blockIdx.x * 128;
    float acc[4][8][4] = {};
    gemm_pipe<128, 2, 4, 8, 136>(g_ctx + (size_t)bm * DM, DM, g_wo + bn, DM, DM, sm, acc);

    const int lane = threadIdx.x & 31, wid = threadIdx.x >> 5;
    const int wm = (wid & 1) * 64, wn = (wid >> 1) * 64;
    const int r = lane >> 2, cq = lane & 3;
    #pragma unroll
    for (int mf = 0; mf < 4; mf++) {
        #pragma unroll
        for (int nf = 0; nf < 8; nf++) {
            int row = bm + wm + mf * 16 + r;
            int col = bn + wn + nf * 8 + 2 * cq;
            float2 bia = *(const float2*)&bo[col];
            float2 q0 = *(const float2*)&Qres[(size_t)row * DM + col];
            float2 q1 = *(const float2*)&Qres[(size_t)(row + 8) * DM + col];
            *(float2*)&g_y[(size_t)row * DM + col] =
                make_float2(acc[mf][nf][0] + bia.x + q0.x, acc[mf][nf][1] + bia.y + q0.y);
            *(float2*)&g_y[(size_t)(row + 8) * DM + col] =
                make_float2(acc[mf][nf][2] + bia.x + q1.x, acc[mf][nf][3] + bia.y + q1.y);
        }
    }
}

// ---------------------------------------------------------------------------
// 5) LayerNorm over last dim (1024), biased variance, eps 1e-5. Grid 4096x256.
// ---------------------------------------------------------------------------
__global__ __launch_bounds__(256) void ln_kernel(
    const float* __restrict__ gamma, const float* __restrict__ beta,
    float* __restrict__ out)
{
    const float4* row = (const float4*)(g_y + (size_t)blockIdx.x * DM);
    const int t = threadIdx.x, lane = t & 31, w = t >> 5;
    __shared__ float s1[8], s2[8];
    float4 x = row[t];
    float a = x.x + x.y + x.z + x.w;
    float b = x.x * x.x + x.y * x.y + x.z * x.z + x.w * x.w;
    #pragma unroll
    for (int o = 16; o > 0; o >>= 1) {
        a += __shfl_xor_sync(0xffffffffu, a, o);
        b += __shfl_xor_sync(0xffffffffu, b, o);
    }
    if (lane == 0) { s1[w] = a; s2[w] = b; }
    __syncthreads();
    float A = 0.f, B2 = 0.f;
    #pragma unroll
    for (int i = 0; i < 8; i++) { A += s1[i]; B2 += s2[i]; }
    float mean = A * (1.0f / 1024.0f);
    float var = B2 * (1.0f / 1024.0f) - mean * mean;
    float rstd = rsqrtf(var + 1e-5f);
    float4 g = ((const float4*)gamma)[t];
    float4 be = ((const float4*)beta)[t];
    float4 o4;
    o4.x = (x.x - mean) * rstd * g.x + be.x;
    o4.y = (x.y - mean) * rstd * g.y + be.y;
    o4.z = (x.z - mean) * rstd * g.z + be.z;
    o4.w = (x.w - mean) * rstd * g.w + be.w;
    ((float4*)(out + (size_t)blockIdx.x * DM))[t] = o4;
}

// ---------------------------------------------------------------------------
extern "C" void kernel_launch(void* const* d_in, const int* in_sizes, int n_in,
                              void* d_out, int out_size) {
    const float* Qin   = (const float*)d_in[0];
    const void*  mask  = d_in[3];
    const float* Wq    = (const float*)d_in[4];
    const float* bq    = (const float*)d_in[5];
    const float* Wk    = (const float*)d_in[6];
    const float* bk    = (const float*)d_in[7];
    const float* Wv    = (const float*)d_in[8];
    const float* bv    = (const float*)d_in[9];
    const float* Wo    = (const float*)d_in[10];
    const float* bo    = (const float*)d_in[11];
    const float* gamma = (const float*)d_in[12];
    const float* beta  = (const float*)d_in[13];
    float* out = (float*)d_out;

    const int use_ext = (out_size > OUT_ELEMS) ? 1 : 0;
    float* attn_ext = out + OUT_ELEMS;

    cudaFuncSetAttribute(qkv_gemm, cudaFuncAttributeMaxDynamicSharedMemorySize, QKV_SMEM_BYTES);
    cudaFuncSetAttribute(outproj_kernel, cudaFuncAttributeMaxDynamicSharedMemorySize, QKV_SMEM_BYTES);
    cudaFuncSetAttribute(scores_softmax_kernel, cudaFuncAttributeMaxDynamicSharedMemorySize, FUS_SMEM_BYTES);
    cudaFuncSetAttribute(context_kernel, cudaFuncAttributeMaxDynamicSharedMemorySize, CTX_SMEM_BYTES);

    detect_mask_kernel<<<1, 32>>>((const unsigned*)mask);
    round_inputs_kernel<<<dim3(MROWS * DM / 4 / 256, 1, 3), 256>>>(
        Qin, (const float*)d_in[1], (const float*)d_in[2]);
    round_weights_kernel<<<dim3(DM * DM / 4 / 256, 1, 4), 256>>>(Wq, Wk, Wv, Wo);
    qkv_gemm<<<dim3(8, 32, 3), 128, QKV_SMEM_BYTES>>>(bq, bk, bv);
    scores_softmax_kernel<<<dim3(32, 64), 256, FUS_SMEM_BYTES>>>(mask, attn_ext, use_ext);
    context_kernel<<<dim3(1, 4, 64), 256, CTX_SMEM_BYTES>>>(attn_ext, use_ext);
    outproj_kernel<<<dim3(8, 32), 128, QKV_SMEM_BYTES>>>(bo, Qin);
    ln_kernel<<<dim3(MROWS), 256>>>(gamma, beta, out);
    (void)in_sizes; (void)n_in;
}